// round 7
// baseline (speedup 1.0000x reference)
#include <cuda_runtime.h>
#include <math.h>
#include <float.h>
#include <stdint.h>

#define N_NODES 100000
#define IN_DIM  256
#define HID     128
#define OUT_DIM 40
#define E_MAX   3200000
#define NB_SCAN ((N_NODES + 1023) / 1024)   // 98

typedef unsigned long long u64;

// ---------------- scratch (device globals, allocation-free) ----------------
__device__ int   g_cnt_in[N_NODES];
__device__ int   g_cnt_out[N_NODES];
__device__ int   g_incl[N_NODES];
__device__ int   g_bsum[NB_SCAN];
__device__ int   g_boff[NB_SCAN];
__device__ int   g_row_off[N_NODES + 1];
__device__ int   g_cursor[N_NODES];
__device__ int   g_csr_src[E_MAX];
__device__ float g_buf1[(size_t)N_NODES * HID];  // h1 ; later x2 (stride 40)
__device__ float g_buf2[(size_t)N_NODES * HID];  // x1

// ---------------- packed fp32x2 helpers (Blackwell FFMA2) ----------------
__device__ __forceinline__ u64 ffma2(u64 a, u64 b, u64 c) {
    u64 d;
    asm("fma.rn.f32x2 %0, %1, %2, %3;" : "=l"(d) : "l"(a), "l"(b), "l"(c));
    return d;
}
__device__ __forceinline__ u64 dup2(float v) {
    unsigned int b = __float_as_uint(v);
    return ((u64)b << 32) | (u64)b;
}
__device__ __forceinline__ float lo2(u64 v) { return __uint_as_float((unsigned int)v); }
__device__ __forceinline__ float hi2(u64 v) { return __uint_as_float((unsigned int)(v >> 32)); }

__device__ __forceinline__ uint32_t smem_u32(const void* p) {
    uint32_t a;
    asm("{ .reg .u64 t; cvta.to.shared.u64 t, %1; cvt.u32.u64 %0, t; }" : "=r"(a) : "l"(p));
    return a;
}
__device__ __forceinline__ void cp_async16(uint32_t smem_dst, const void* gmem_src) {
    asm volatile("cp.async.ca.shared.global [%0], [%1], 16;" :: "r"(smem_dst), "l"(gmem_src) : "memory");
}
__device__ __forceinline__ void cp_commit() {
    asm volatile("cp.async.commit_group;" ::: "memory");
}
template <int N>
__device__ __forceinline__ void cp_wait() {
    asm volatile("cp.async.wait_group %0;" :: "n"(N) : "memory");
}

// ---------------------------------------------------------------------------
__global__ void zero_counts_kernel() {
    int i = blockIdx.x * blockDim.x + threadIdx.x;
    if (i < N_NODES) { g_cnt_in[i] = 0; g_cnt_out[i] = 0; }
}

__global__ void degree_kernel(const int4* __restrict__ src4, const int4* __restrict__ dst4, int E4) {
    int i = blockIdx.x * blockDim.x + threadIdx.x;
    if (i >= E4) return;
    int4 s = src4[i], d = dst4[i];
    atomicAdd(&g_cnt_out[s.x], 1); atomicAdd(&g_cnt_out[s.y], 1);
    atomicAdd(&g_cnt_out[s.z], 1); atomicAdd(&g_cnt_out[s.w], 1);
    atomicAdd(&g_cnt_in[d.x], 1);  atomicAdd(&g_cnt_in[d.y], 1);
    atomicAdd(&g_cnt_in[d.z], 1);  atomicAdd(&g_cnt_in[d.w], 1);
}

// ---------------- CSR build (shfl scans) ----------------
__global__ __launch_bounds__(1024) void scan1_kernel() {
    __shared__ int wsum[32];
    int tid = threadIdx.x, lane = tid & 31, wid = tid >> 5;
    int i = blockIdx.x * 1024 + tid;
    int v = (i < N_NODES) ? g_cnt_in[i] : 0;
    int x = v;
#pragma unroll
    for (int o = 1; o < 32; o <<= 1) {
        int t = __shfl_up_sync(0xffffffff, x, o);
        if (lane >= o) x += t;
    }
    if (lane == 31) wsum[wid] = x;
    __syncthreads();
    if (wid == 0) {
        int w = wsum[lane];
#pragma unroll
        for (int o = 1; o < 32; o <<= 1) {
            int t = __shfl_up_sync(0xffffffff, w, o);
            if (lane >= o) w += t;
        }
        wsum[lane] = w;
    }
    __syncthreads();
    int base = (wid > 0) ? wsum[wid - 1] : 0;
    x += base;
    if (i < N_NODES) g_incl[i] = x;
    if (tid == 1023) g_bsum[blockIdx.x] = x;
}

__global__ __launch_bounds__(128) void scan2_kernel() {
    __shared__ int wsum[4];
    int tid = threadIdx.x, lane = tid & 31, wid = tid >> 5;
    int v = (tid < NB_SCAN) ? g_bsum[tid] : 0;
    int x = v;
#pragma unroll
    for (int o = 1; o < 32; o <<= 1) {
        int t = __shfl_up_sync(0xffffffff, x, o);
        if (lane >= o) x += t;
    }
    if (lane == 31) wsum[wid] = x;
    __syncthreads();
    int base = 0;
#pragma unroll
    for (int w = 0; w < 4; w++) base += (w < wid) ? wsum[w] : 0;
    if (tid < NB_SCAN) g_boff[tid] = x + base - v;   // exclusive
}

__global__ void scan3_kernel() {
    int i = blockIdx.x * blockDim.x + threadIdx.x;
    if (i >= N_NODES) return;
    int boff = g_boff[i >> 10];
    int excl = g_incl[i] - g_cnt_in[i] + boff;
    g_row_off[i] = excl;
    g_cursor[i]  = excl;
    if (i == N_NODES - 1) g_row_off[N_NODES] = g_incl[i] + boff;
}

__global__ void scatter_kernel(const int4* __restrict__ src4, const int4* __restrict__ dst4, int E4) {
    int i = blockIdx.x * blockDim.x + threadIdx.x;
    if (i >= E4) return;
    int4 s = src4[i], d = dst4[i];
    g_csr_src[atomicAdd(&g_cursor[d.x], 1)] = s.x;
    g_csr_src[atomicAdd(&g_cursor[d.y], 1)] = s.y;
    g_csr_src[atomicAdd(&g_cursor[d.z], 1)] = s.z;
    g_csr_src[atomicAdd(&g_cursor[d.w], 1)] = s.w;
}

// ---------------------------------------------------------------------------
// GEMM1 (FFMA2, cp.async double-buffered, warp 4x8 remap, paired A loads)
// g_buf1 = (h @ W1) * deg_out^-1/2. BM=64, BN=128, BK=16, 128 threads.
// As2 layout [k][row] (row contiguous, +2 u64 pad) so two A pairs load as
// one LDS.128; warp covers 4 tm x 8 tn threads so B LDS.128 has 4-way dedup.
// ---------------------------------------------------------------------------
#define G1_BM 64
#define G1_BK 16
#define G1_NIT (IN_DIM / G1_BK)   // 16
__global__ __launch_bounds__(128, 4) void gemm1_kernel(const float* __restrict__ A,
                                                       const float* __restrict__ B) {
    __shared__ __align__(16) u64 As2[2][G1_BK][G1_BM + 2];  // 16.9KB
    __shared__ __align__(16) float Bs[2][G1_BK][HID];       // 16KB
    const int tid = threadIdx.x;
    const int w = tid >> 5, lane = tid & 31;
    const int row0 = blockIdx.x * G1_BM;
    // warp remap: 4 tm-threads x 8 tn-threads per warp
    const int tm0 = (((w >> 1) * 4) + (lane >> 3)) * 8;   // 0..56
    const int tn0 = (((w & 1) * 8) + (lane & 7)) * 8;     // 0..120
    const int ar = tid >> 2, ac = tid & 3;   // A staging: rows ar, ar+32; chunk ac
    const int br = tid >> 5, bc = tid & 31;  // B staging: rows br+4i; 16B chunk bc

    const int rowA0 = row0 + ar, rowA1 = row0 + ar + 32;
    const float* pA0 = A + (size_t)rowA0 * IN_DIM + ac * 4;
    const float* pA1 = A + (size_t)rowA1 * IN_DIM + ac * 4;
    const bool okA0 = rowA0 < N_NODES, okA1 = rowA1 < N_NODES;

    u64 acc[8][4];
#pragma unroll
    for (int i = 0; i < 8; i++)
#pragma unroll
        for (int j = 0; j < 4; j++) acc[i][j] = 0ull;

    float4 pa0, pa1;
    const float4 z4 = make_float4(0.f, 0.f, 0.f, 0.f);

    // ---- prologue: stage tile 0 into buffer 0 ----
    pa0 = okA0 ? *reinterpret_cast<const float4*>(pA0) : z4;
    pa1 = okA1 ? *reinterpret_cast<const float4*>(pA1) : z4;
    As2[0][ac * 4 + 0][ar] = dup2(pa0.x);
    As2[0][ac * 4 + 1][ar] = dup2(pa0.y);
    As2[0][ac * 4 + 2][ar] = dup2(pa0.z);
    As2[0][ac * 4 + 3][ar] = dup2(pa0.w);
    As2[0][ac * 4 + 0][ar + 32] = dup2(pa1.x);
    As2[0][ac * 4 + 1][ar + 32] = dup2(pa1.y);
    As2[0][ac * 4 + 2][ar + 32] = dup2(pa1.z);
    As2[0][ac * 4 + 3][ar + 32] = dup2(pa1.w);
#pragma unroll
    for (int i = 0; i < 4; i++)
        cp_async16(smem_u32(&Bs[0][br + 4 * i][bc * 4]), B + (size_t)(br + 4 * i) * HID + bc * 4);
    cp_commit();

    int cur = 0;
    for (int it = 0; it < G1_NIT; it++) {
        const bool more = (it + 1 < G1_NIT);
        if (more) {
            const int k1 = (it + 1) * G1_BK;
            pa0 = okA0 ? *reinterpret_cast<const float4*>(pA0 + k1) : z4;
            pa1 = okA1 ? *reinterpret_cast<const float4*>(pA1 + k1) : z4;
#pragma unroll
            for (int i = 0; i < 4; i++)
                cp_async16(smem_u32(&Bs[cur ^ 1][br + 4 * i][bc * 4]),
                           B + (size_t)(k1 + br + 4 * i) * HID + bc * 4);
            cp_commit();
            cp_wait<1>();
        } else {
            cp_wait<0>();
        }
        __syncthreads();

#pragma unroll
        for (int k = 0; k < G1_BK; k++) {
            u64 ra[8];
#pragma unroll
            for (int i = 0; i < 8; i += 2) {
                ulonglong2 t = *reinterpret_cast<const ulonglong2*>(&As2[cur][k][tm0 + i]);
                ra[i] = t.x; ra[i + 1] = t.y;
            }
            ulonglong2 t0 = *reinterpret_cast<const ulonglong2*>(&Bs[cur][k][tn0]);
            ulonglong2 t1 = *reinterpret_cast<const ulonglong2*>(&Bs[cur][k][tn0 + 4]);
            u64 rb[4] = {t0.x, t0.y, t1.x, t1.y};
#pragma unroll
            for (int i = 0; i < 8; i++)
#pragma unroll
                for (int j = 0; j < 4; j++) acc[i][j] = ffma2(ra[i], rb[j], acc[i][j]);
        }

        if (more) {
            const int nb = cur ^ 1;
            As2[nb][ac * 4 + 0][ar] = dup2(pa0.x);
            As2[nb][ac * 4 + 1][ar] = dup2(pa0.y);
            As2[nb][ac * 4 + 2][ar] = dup2(pa0.z);
            As2[nb][ac * 4 + 3][ar] = dup2(pa0.w);
            As2[nb][ac * 4 + 0][ar + 32] = dup2(pa1.x);
            As2[nb][ac * 4 + 1][ar + 32] = dup2(pa1.y);
            As2[nb][ac * 4 + 2][ar + 32] = dup2(pa1.z);
            As2[nb][ac * 4 + 3][ar + 32] = dup2(pa1.w);
        }
        cur ^= 1;
    }

#pragma unroll
    for (int i = 0; i < 8; i++) {
        int row = row0 + tm0 + i;
        if (row >= N_NODES) break;
        float s = rsqrtf(fmaxf((float)g_cnt_out[row], 1.0f));
        float4 v0 = make_float4(lo2(acc[i][0]) * s, hi2(acc[i][0]) * s,
                                lo2(acc[i][1]) * s, hi2(acc[i][1]) * s);
        float4 v1 = make_float4(lo2(acc[i][2]) * s, hi2(acc[i][2]) * s,
                                lo2(acc[i][3]) * s, hi2(acc[i][3]) * s);
        *reinterpret_cast<float4*>(g_buf1 + (size_t)row * HID + tn0)     = v0;
        *reinterpret_cast<float4*>(g_buf1 + (size_t)row * HID + tn0 + 4) = v1;
    }
}

// ---------------------------------------------------------------------------
// SpMM1 (pull, CSR): warp per dst node, fused norm+bias+relu.
// ---------------------------------------------------------------------------
__global__ __launch_bounds__(256) void spmm1_csr_kernel(const float* __restrict__ b1) {
    int n = (blockIdx.x * blockDim.x + threadIdx.x) >> 5;
    if (n >= N_NODES) return;
    int lane = threadIdx.x & 31;
    int start = g_row_off[n];
    int end   = g_row_off[n + 1];

    float ax = 0.f, ay = 0.f, az = 0.f, aw = 0.f;
    for (int j = start; j < end; j += 32) {
        int s = 0;
        if (j + lane < end) s = __ldg(&g_csr_src[j + lane]);
        int cnt = min(32, end - j);
        for (int k = 0; k < cnt; k++) {
            int sv = __shfl_sync(0xffffffff, s, k);
            float4 v = *reinterpret_cast<const float4*>(g_buf1 + (size_t)sv * HID + lane * 4);
            ax += v.x; ay += v.y; az += v.z; aw += v.w;
        }
    }

    float sc = rsqrtf(fmaxf((float)(end - start), 1.0f));
    float4 bb = *reinterpret_cast<const float4*>(b1 + lane * 4);
    float4 o;
    o.x = fmaxf(ax * sc + bb.x, 0.f);
    o.y = fmaxf(ay * sc + bb.y, 0.f);
    o.z = fmaxf(az * sc + bb.z, 0.f);
    o.w = fmaxf(aw * sc + bb.w, 0.f);
    *reinterpret_cast<float4*>(g_buf2 + (size_t)n * HID + lane * 4) = o;
}

// ---------------------------------------------------------------------------
// GEMM2 (FFMA2): g_buf1[:, :40] = (x1 @ W2) * rsqrt(max(deg_out,1))
// ---------------------------------------------------------------------------
__global__ __launch_bounds__(128) void gemm2_kernel(const float* __restrict__ W2) {
    __shared__ float Ws[HID * OUT_DIM];
    const int tid = threadIdx.x;
    for (int i = tid; i < HID * OUT_DIM; i += 128) Ws[i] = W2[i];
    __syncthreads();

    int row = blockIdx.x * 128 + tid;
    if (row >= N_NODES) return;

    u64 acc[OUT_DIM / 2];
#pragma unroll
    for (int c = 0; c < OUT_DIM / 2; c++) acc[c] = 0ull;

    const float* xr = g_buf2 + (size_t)row * HID;
#pragma unroll 4
    for (int k = 0; k < HID; k += 4) {
        float4 xv = *reinterpret_cast<const float4*>(xr + k);
        u64 xs0 = dup2(xv.x), xs1 = dup2(xv.y), xs2 = dup2(xv.z), xs3 = dup2(xv.w);
        const u64* w0 = reinterpret_cast<const u64*>(&Ws[(k + 0) * OUT_DIM]);
        const u64* w1 = reinterpret_cast<const u64*>(&Ws[(k + 1) * OUT_DIM]);
        const u64* w2 = reinterpret_cast<const u64*>(&Ws[(k + 2) * OUT_DIM]);
        const u64* w3 = reinterpret_cast<const u64*>(&Ws[(k + 3) * OUT_DIM]);
#pragma unroll
        for (int c = 0; c < OUT_DIM / 2; c++) {
            acc[c] = ffma2(xs0, w0[c], acc[c]);
            acc[c] = ffma2(xs1, w1[c], acc[c]);
            acc[c] = ffma2(xs2, w2[c], acc[c]);
            acc[c] = ffma2(xs3, w3[c], acc[c]);
        }
    }

    float s = rsqrtf(fmaxf((float)g_cnt_out[row], 1.0f));
    float* o = g_buf1 + (size_t)row * OUT_DIM;
#pragma unroll
    for (int c = 0; c < OUT_DIM / 2; c += 2) {
        float4 v = make_float4(lo2(acc[c]) * s, hi2(acc[c]) * s,
                               lo2(acc[c + 1]) * s, hi2(acc[c + 1]) * s);
        *reinterpret_cast<float4*>(o + 2 * c) = v;
    }
}

// ---------------------------------------------------------------------------
// SpMM2 (pull, CSR) + fused norm + bias + log_softmax. Dual-edge per iter.
// ---------------------------------------------------------------------------
__global__ __launch_bounds__(256) void spmm2_csr_kernel(float* __restrict__ out,
                                                        const float* __restrict__ b2) {
    int n = (blockIdx.x * blockDim.x + threadIdx.x) >> 5;
    if (n >= N_NODES) return;
    int lane = threadIdx.x & 31;
    int half = lane >> 4;
    int hl   = lane & 15;
    bool act = hl < (OUT_DIM / 4);
    int start = g_row_off[n];
    int end   = g_row_off[n + 1];

    float ax = 0.f, ay = 0.f, az = 0.f, aw = 0.f;
    for (int j = start; j < end; j += 32) {
        int s = 0;
        if (j + lane < end) s = __ldg(&g_csr_src[j + lane]);
        int cnt = min(32, end - j);
        for (int k = 0; k < cnt; k += 2) {
            int idx = k + half;
            bool ok = act && (idx < cnt);
            int sv = __shfl_sync(0xffffffff, s, idx < cnt ? idx : k);
            if (ok) {
                float4 v = *reinterpret_cast<const float4*>(g_buf1 + (size_t)sv * OUT_DIM + hl * 4);
                ax += v.x; ay += v.y; az += v.z; aw += v.w;
            }
        }
    }
    ax += __shfl_down_sync(0xffffffff, ax, 16);
    ay += __shfl_down_sync(0xffffffff, ay, 16);
    az += __shfl_down_sync(0xffffffff, az, 16);
    aw += __shfl_down_sync(0xffffffff, aw, 16);

    bool fin = (lane < OUT_DIM / 4);
    float sc = rsqrtf(fmaxf((float)(end - start), 1.0f));
    float4 x = make_float4(-FLT_MAX, -FLT_MAX, -FLT_MAX, -FLT_MAX);
    if (fin) {
        float4 bb = *reinterpret_cast<const float4*>(b2 + lane * 4);
        x.x = ax * sc + bb.x;
        x.y = ay * sc + bb.y;
        x.z = az * sc + bb.z;
        x.w = aw * sc + bb.w;
    }

    float m = fmaxf(fmaxf(x.x, x.y), fmaxf(x.z, x.w));
#pragma unroll
    for (int o = 16; o > 0; o >>= 1) m = fmaxf(m, __shfl_xor_sync(0xffffffff, m, o));

    float se = 0.f;
    if (fin) se = expf(x.x - m) + expf(x.y - m) + expf(x.z - m) + expf(x.w - m);
#pragma unroll
    for (int o = 16; o > 0; o >>= 1) se += __shfl_xor_sync(0xffffffff, se, o);

    float lse = m + logf(se);
    if (fin) {
        float4 r = make_float4(x.x - lse, x.y - lse, x.z - lse, x.w - lse);
        *reinterpret_cast<float4*>(out + (size_t)n * OUT_DIM + lane * 4) = r;
    }
}

// ---------------------------------------------------------------------------
extern "C" void kernel_launch(void* const* d_in, const int* in_sizes, int n_in,
                              void* d_out, int out_size) {
    const float* h  = (const float*)d_in[0];
    const float* W1 = (const float*)d_in[1];
    const float* b1 = (const float*)d_in[2];
    const float* W2 = (const float*)d_in[3];
    const float* b2 = (const float*)d_in[4];
    const int* src  = (const int*)d_in[5];
    const int* dst  = (const int*)d_in[6];
    float* out      = (float*)d_out;
    const int E     = in_sizes[5];
    const int E4    = E / 4;

    zero_counts_kernel<<<(N_NODES + 255) / 256, 256>>>();                                    // 1
    degree_kernel<<<(E4 + 255) / 256, 256>>>((const int4*)src, (const int4*)dst, E4);        // 2
    scan1_kernel<<<NB_SCAN, 1024>>>();                                                       // 3
    gemm1_kernel<<<(N_NODES + G1_BM - 1) / G1_BM, 128>>>(h, W1);                             // 4 (profiled)
    scan2_kernel<<<1, 128>>>();                                                              // 5
    scan3_kernel<<<(N_NODES + 255) / 256, 256>>>();                                          // 6
    scatter_kernel<<<(E4 + 255) / 256, 256>>>((const int4*)src, (const int4*)dst, E4);       // 7
    spmm1_csr_kernel<<<(N_NODES * 32 + 255) / 256, 256>>>(b1);                               // 8
    gemm2_kernel<<<(N_NODES + 127) / 128, 128>>>(W2);                                        // 9
    spmm2_csr_kernel<<<(N_NODES * 32 + 255) / 256, 256>>>(out, b2);                          // 10
}

// round 9
// speedup vs baseline: 1.0693x; 1.0693x over previous
#include <cuda_runtime.h>
#include <cuda_fp16.h>
#include <math.h>
#include <float.h>
#include <stdint.h>

#define N_NODES 100000
#define IN_DIM  256
#define HID     128
#define OUT_DIM 40
#define E_MAX   3200000
#define NB_SCAN ((N_NODES + 1023) / 1024)   // 98

typedef unsigned long long u64;

// ---------------- scratch (device globals, allocation-free) ----------------
__device__ int   g_cnt_in[N_NODES];
__device__ int   g_cnt_out[N_NODES];
__device__ int   g_incl[N_NODES];
__device__ int   g_bsum[NB_SCAN];
__device__ int   g_boff[NB_SCAN];
__device__ int   g_row_off[N_NODES + 1];
__device__ int   g_cursor[N_NODES];
__device__ int   g_csr_src[E_MAX];
__device__ __half g_h1[(size_t)N_NODES * HID];     // h1 fp16 (layer-1 pre-agg)
__device__ __half g_x2[(size_t)N_NODES * OUT_DIM]; // x2 fp16 (layer-2 pre-agg)
__device__ float  g_buf2[(size_t)N_NODES * HID];   // x1 fp32

// ---------------- packed fp32x2 helpers (Blackwell FFMA2) ----------------
__device__ __forceinline__ u64 ffma2(u64 a, u64 b, u64 c) {
    u64 d;
    asm("fma.rn.f32x2 %0, %1, %2, %3;" : "=l"(d) : "l"(a), "l"(b), "l"(c));
    return d;
}
__device__ __forceinline__ u64 dup2(float v) {
    unsigned int b = __float_as_uint(v);
    return ((u64)b << 32) | (u64)b;
}
__device__ __forceinline__ float lo2(u64 v) { return __uint_as_float((unsigned int)v); }
__device__ __forceinline__ float hi2(u64 v) { return __uint_as_float((unsigned int)(v >> 32)); }

__device__ __forceinline__ uint32_t h2u(__half2 h) {
    uint32_t u;
    memcpy(&u, &h, 4);
    return u;
}

__device__ __forceinline__ uint32_t smem_u32(const void* p) {
    uint32_t a;
    asm("{ .reg .u64 t; cvta.to.shared.u64 t, %1; cvt.u32.u64 %0, t; }" : "=r"(a) : "l"(p));
    return a;
}
__device__ __forceinline__ void cp_async16(uint32_t smem_dst, const void* gmem_src) {
    asm volatile("cp.async.ca.shared.global [%0], [%1], 16;" :: "r"(smem_dst), "l"(gmem_src) : "memory");
}
__device__ __forceinline__ void cp_commit() {
    asm volatile("cp.async.commit_group;" ::: "memory");
}
template <int N>
__device__ __forceinline__ void cp_wait() {
    asm volatile("cp.async.wait_group %0;" :: "n"(N) : "memory");
}

// ---------------------------------------------------------------------------
__global__ void zero_counts_kernel() {
    int i = blockIdx.x * blockDim.x + threadIdx.x;
    if (i < N_NODES) { g_cnt_in[i] = 0; g_cnt_out[i] = 0; }
}

__global__ void degree_kernel(const int4* __restrict__ src4, const int4* __restrict__ dst4, int E4) {
    int i = blockIdx.x * blockDim.x + threadIdx.x;
    if (i >= E4) return;
    int4 s = src4[i], d = dst4[i];
    atomicAdd(&g_cnt_out[s.x], 1); atomicAdd(&g_cnt_out[s.y], 1);
    atomicAdd(&g_cnt_out[s.z], 1); atomicAdd(&g_cnt_out[s.w], 1);
    atomicAdd(&g_cnt_in[d.x], 1);  atomicAdd(&g_cnt_in[d.y], 1);
    atomicAdd(&g_cnt_in[d.z], 1);  atomicAdd(&g_cnt_in[d.w], 1);
}

// ---------------- CSR build (shfl scans) ----------------
__global__ __launch_bounds__(1024) void scan1_kernel() {
    __shared__ int wsum[32];
    int tid = threadIdx.x, lane = tid & 31, wid = tid >> 5;
    int i = blockIdx.x * 1024 + tid;
    int v = (i < N_NODES) ? g_cnt_in[i] : 0;
    int x = v;
#pragma unroll
    for (int o = 1; o < 32; o <<= 1) {
        int t = __shfl_up_sync(0xffffffff, x, o);
        if (lane >= o) x += t;
    }
    if (lane == 31) wsum[wid] = x;
    __syncthreads();
    if (wid == 0) {
        int w = wsum[lane];
#pragma unroll
        for (int o = 1; o < 32; o <<= 1) {
            int t = __shfl_up_sync(0xffffffff, w, o);
            if (lane >= o) w += t;
        }
        wsum[lane] = w;
    }
    __syncthreads();
    int base = (wid > 0) ? wsum[wid - 1] : 0;
    x += base;
    if (i < N_NODES) g_incl[i] = x;
    if (tid == 1023) g_bsum[blockIdx.x] = x;
}

__global__ __launch_bounds__(128) void scan2_kernel() {
    __shared__ int wsum[4];
    int tid = threadIdx.x, lane = tid & 31, wid = tid >> 5;
    int v = (tid < NB_SCAN) ? g_bsum[tid] : 0;
    int x = v;
#pragma unroll
    for (int o = 1; o < 32; o <<= 1) {
        int t = __shfl_up_sync(0xffffffff, x, o);
        if (lane >= o) x += t;
    }
    if (lane == 31) wsum[wid] = x;
    __syncthreads();
    int base = 0;
#pragma unroll
    for (int w = 0; w < 4; w++) base += (w < wid) ? wsum[w] : 0;
    if (tid < NB_SCAN) g_boff[tid] = x + base - v;   // exclusive
}

__global__ void scan3_kernel() {
    int i = blockIdx.x * blockDim.x + threadIdx.x;
    if (i >= N_NODES) return;
    int boff = g_boff[i >> 10];
    int excl = g_incl[i] - g_cnt_in[i] + boff;
    g_row_off[i] = excl;
    g_cursor[i]  = excl;
    if (i == N_NODES - 1) g_row_off[N_NODES] = g_incl[i] + boff;
}

__global__ void scatter_kernel(const int4* __restrict__ src4, const int4* __restrict__ dst4, int E4) {
    int i = blockIdx.x * blockDim.x + threadIdx.x;
    if (i >= E4) return;
    int4 s = src4[i], d = dst4[i];
    g_csr_src[atomicAdd(&g_cursor[d.x], 1)] = s.x;
    g_csr_src[atomicAdd(&g_cursor[d.y], 1)] = s.y;
    g_csr_src[atomicAdd(&g_cursor[d.z], 1)] = s.z;
    g_csr_src[atomicAdd(&g_cursor[d.w], 1)] = s.w;
}

// ---------------------------------------------------------------------------
// GEMM1 (FFMA2, cp.async double-buffered): g_h1 = fp16((h @ W1) * deg_out^-1/2)
// ---------------------------------------------------------------------------
#define G1_BM 64
#define G1_BK 16
#define G1_NIT (IN_DIM / G1_BK)   // 16
__global__ __launch_bounds__(128, 4) void gemm1_kernel(const float* __restrict__ A,
                                                       const float* __restrict__ B) {
    __shared__ __align__(16) u64 As2[2][G1_BK][G1_BM + 2];
    __shared__ __align__(16) float Bs[2][G1_BK][HID];
    const int tid = threadIdx.x;
    const int w = tid >> 5, lane = tid & 31;
    const int row0 = blockIdx.x * G1_BM;
    const int tm0 = (((w >> 1) * 4) + (lane >> 3)) * 8;
    const int tn0 = (((w & 1) * 8) + (lane & 7)) * 8;
    const int ar = tid >> 2, ac = tid & 3;
    const int br = tid >> 5, bc = tid & 31;

    const int rowA0 = row0 + ar, rowA1 = row0 + ar + 32;
    const float* pA0 = A + (size_t)rowA0 * IN_DIM + ac * 4;
    const float* pA1 = A + (size_t)rowA1 * IN_DIM + ac * 4;
    const bool okA0 = rowA0 < N_NODES, okA1 = rowA1 < N_NODES;

    u64 acc[8][4];
#pragma unroll
    for (int i = 0; i < 8; i++)
#pragma unroll
        for (int j = 0; j < 4; j++) acc[i][j] = 0ull;

    float4 pa0, pa1;
    const float4 z4 = make_float4(0.f, 0.f, 0.f, 0.f);

    pa0 = okA0 ? *reinterpret_cast<const float4*>(pA0) : z4;
    pa1 = okA1 ? *reinterpret_cast<const float4*>(pA1) : z4;
    As2[0][ac * 4 + 0][ar] = dup2(pa0.x);
    As2[0][ac * 4 + 1][ar] = dup2(pa0.y);
    As2[0][ac * 4 + 2][ar] = dup2(pa0.z);
    As2[0][ac * 4 + 3][ar] = dup2(pa0.w);
    As2[0][ac * 4 + 0][ar + 32] = dup2(pa1.x);
    As2[0][ac * 4 + 1][ar + 32] = dup2(pa1.y);
    As2[0][ac * 4 + 2][ar + 32] = dup2(pa1.z);
    As2[0][ac * 4 + 3][ar + 32] = dup2(pa1.w);
#pragma unroll
    for (int i = 0; i < 4; i++)
        cp_async16(smem_u32(&Bs[0][br + 4 * i][bc * 4]), B + (size_t)(br + 4 * i) * HID + bc * 4);
    cp_commit();

    int cur = 0;
    for (int it = 0; it < G1_NIT; it++) {
        const bool more = (it + 1 < G1_NIT);
        if (more) {
            const int k1 = (it + 1) * G1_BK;
            pa0 = okA0 ? *reinterpret_cast<const float4*>(pA0 + k1) : z4;
            pa1 = okA1 ? *reinterpret_cast<const float4*>(pA1 + k1) : z4;
#pragma unroll
            for (int i = 0; i < 4; i++)
                cp_async16(smem_u32(&Bs[cur ^ 1][br + 4 * i][bc * 4]),
                           B + (size_t)(k1 + br + 4 * i) * HID + bc * 4);
            cp_commit();
            cp_wait<1>();
        } else {
            cp_wait<0>();
        }
        __syncthreads();

#pragma unroll
        for (int k = 0; k < G1_BK; k++) {
            u64 ra[8];
#pragma unroll
            for (int i = 0; i < 8; i += 2) {
                ulonglong2 t = *reinterpret_cast<const ulonglong2*>(&As2[cur][k][tm0 + i]);
                ra[i] = t.x; ra[i + 1] = t.y;
            }
            ulonglong2 t0 = *reinterpret_cast<const ulonglong2*>(&Bs[cur][k][tn0]);
            ulonglong2 t1 = *reinterpret_cast<const ulonglong2*>(&Bs[cur][k][tn0 + 4]);
            u64 rb[4] = {t0.x, t0.y, t1.x, t1.y};
#pragma unroll
            for (int i = 0; i < 8; i++)
#pragma unroll
                for (int j = 0; j < 4; j++) acc[i][j] = ffma2(ra[i], rb[j], acc[i][j]);
        }

        if (more) {
            const int nb = cur ^ 1;
            As2[nb][ac * 4 + 0][ar] = dup2(pa0.x);
            As2[nb][ac * 4 + 1][ar] = dup2(pa0.y);
            As2[nb][ac * 4 + 2][ar] = dup2(pa0.z);
            As2[nb][ac * 4 + 3][ar] = dup2(pa0.w);
            As2[nb][ac * 4 + 0][ar + 32] = dup2(pa1.x);
            As2[nb][ac * 4 + 1][ar + 32] = dup2(pa1.y);
            As2[nb][ac * 4 + 2][ar + 32] = dup2(pa1.z);
            As2[nb][ac * 4 + 3][ar + 32] = dup2(pa1.w);
        }
        cur ^= 1;
    }

    // epilogue: scale by deg_out^-1/2, convert to fp16, one 16B store per row
#pragma unroll
    for (int i = 0; i < 8; i++) {
        int row = row0 + tm0 + i;
        if (row >= N_NODES) break;
        float s = rsqrtf(fmaxf((float)g_cnt_out[row], 1.0f));
        __half2 h0 = __floats2half2_rn(lo2(acc[i][0]) * s, hi2(acc[i][0]) * s);
        __half2 h1 = __floats2half2_rn(lo2(acc[i][1]) * s, hi2(acc[i][1]) * s);
        __half2 h2 = __floats2half2_rn(lo2(acc[i][2]) * s, hi2(acc[i][2]) * s);
        __half2 h3 = __floats2half2_rn(lo2(acc[i][3]) * s, hi2(acc[i][3]) * s);
        uint4 pk = make_uint4(h2u(h0), h2u(h1), h2u(h2), h2u(h3));
        *reinterpret_cast<uint4*>(g_h1 + (size_t)row * HID + tn0) = pk;
    }
}

// ---------------------------------------------------------------------------
// SpMM1 (pull, CSR, fp16 gather): warp per dst node, fused norm+bias+relu.
// Lane owns 4 cols (uint2 = 4 half). fp32 accumulation.
// ---------------------------------------------------------------------------
__global__ __launch_bounds__(256) void spmm1_csr_kernel(const float* __restrict__ b1) {
    int n = (blockIdx.x * blockDim.x + threadIdx.x) >> 5;
    if (n >= N_NODES) return;
    int lane = threadIdx.x & 31;
    int start = g_row_off[n];
    int end   = g_row_off[n + 1];

    float ax = 0.f, ay = 0.f, az = 0.f, aw = 0.f;
    for (int j = start; j < end; j += 32) {
        int s = 0;
        if (j + lane < end) s = __ldg(&g_csr_src[j + lane]);
        int cnt = min(32, end - j);
        for (int k = 0; k < cnt; k++) {
            int sv = __shfl_sync(0xffffffff, s, k);
            uint2 pk = *reinterpret_cast<const uint2*>(g_h1 + (size_t)sv * HID + lane * 4);
            float2 f0 = __half22float2(*reinterpret_cast<__half2*>(&pk.x));
            float2 f1 = __half22float2(*reinterpret_cast<__half2*>(&pk.y));
            ax += f0.x; ay += f0.y; az += f1.x; aw += f1.y;
        }
    }

    float sc = rsqrtf(fmaxf((float)(end - start), 1.0f));
    float4 bb = *reinterpret_cast<const float4*>(b1 + lane * 4);
    float4 o;
    o.x = fmaxf(ax * sc + bb.x, 0.f);
    o.y = fmaxf(ay * sc + bb.y, 0.f);
    o.z = fmaxf(az * sc + bb.z, 0.f);
    o.w = fmaxf(aw * sc + bb.w, 0.f);
    *reinterpret_cast<float4*>(g_buf2 + (size_t)n * HID + lane * 4) = o;
}

// ---------------------------------------------------------------------------
// GEMM2 (FFMA2): g_x2 = fp16((x1 @ W2) * deg_out^-1/2)
// ---------------------------------------------------------------------------
__global__ __launch_bounds__(128) void gemm2_kernel(const float* __restrict__ W2) {
    __shared__ float Ws[HID * OUT_DIM];
    const int tid = threadIdx.x;
    for (int i = tid; i < HID * OUT_DIM; i += 128) Ws[i] = W2[i];
    __syncthreads();

    int row = blockIdx.x * 128 + tid;
    if (row >= N_NODES) return;

    u64 acc[OUT_DIM / 2];
#pragma unroll
    for (int c = 0; c < OUT_DIM / 2; c++) acc[c] = 0ull;

    const float* xr = g_buf2 + (size_t)row * HID;
#pragma unroll 4
    for (int k = 0; k < HID; k += 4) {
        float4 xv = *reinterpret_cast<const float4*>(xr + k);
        u64 xs0 = dup2(xv.x), xs1 = dup2(xv.y), xs2 = dup2(xv.z), xs3 = dup2(xv.w);
        const u64* w0 = reinterpret_cast<const u64*>(&Ws[(k + 0) * OUT_DIM]);
        const u64* w1 = reinterpret_cast<const u64*>(&Ws[(k + 1) * OUT_DIM]);
        const u64* w2 = reinterpret_cast<const u64*>(&Ws[(k + 2) * OUT_DIM]);
        const u64* w3 = reinterpret_cast<const u64*>(&Ws[(k + 3) * OUT_DIM]);
#pragma unroll
        for (int c = 0; c < OUT_DIM / 2; c++) {
            acc[c] = ffma2(xs0, w0[c], acc[c]);
            acc[c] = ffma2(xs1, w1[c], acc[c]);
            acc[c] = ffma2(xs2, w2[c], acc[c]);
            acc[c] = ffma2(xs3, w3[c], acc[c]);
        }
    }

    float s = rsqrtf(fmaxf((float)g_cnt_out[row], 1.0f));
    // 40 halves = 5 uint4 stores (row stride 80B, 16B aligned)
#pragma unroll
    for (int q = 0; q < 5; q++) {
        __half2 h0 = __floats2half2_rn(lo2(acc[q * 4 + 0]) * s, hi2(acc[q * 4 + 0]) * s);
        __half2 h1 = __floats2half2_rn(lo2(acc[q * 4 + 1]) * s, hi2(acc[q * 4 + 1]) * s);
        __half2 h2 = __floats2half2_rn(lo2(acc[q * 4 + 2]) * s, hi2(acc[q * 4 + 2]) * s);
        __half2 h3 = __floats2half2_rn(lo2(acc[q * 4 + 3]) * s, hi2(acc[q * 4 + 3]) * s);
        uint4 pk = make_uint4(h2u(h0), h2u(h1), h2u(h2), h2u(h3));
        *reinterpret_cast<uint4*>(g_x2 + (size_t)row * OUT_DIM + q * 8) = pk;
    }
}

// ---------------------------------------------------------------------------
// SpMM2 (pull, CSR, fp16 gather) + fused norm + bias + log_softmax.
// Dual-edge per iter; lane owns 4 cols via uint2 (4 half).
// ---------------------------------------------------------------------------
__global__ __launch_bounds__(256) void spmm2_csr_kernel(float* __restrict__ out,
                                                        const float* __restrict__ b2) {
    int n = (blockIdx.x * blockDim.x + threadIdx.x) >> 5;
    if (n >= N_NODES) return;
    int lane = threadIdx.x & 31;
    int half = lane >> 4;
    int hl   = lane & 15;
    bool act = hl < (OUT_DIM / 4);
    int start = g_row_off[n];
    int end   = g_row_off[n + 1];

    float ax = 0.f, ay = 0.f, az = 0.f, aw = 0.f;
    for (int j = start; j < end; j += 32) {
        int s = 0;
        if (j + lane < end) s = __ldg(&g_csr_src[j + lane]);
        int cnt = min(32, end - j);
        for (int k = 0; k < cnt; k += 2) {
            int idx = k + half;
            bool ok = act && (idx < cnt);
            int sv = __shfl_sync(0xffffffff, s, idx < cnt ? idx : k);
            if (ok) {
                uint2 pk = *reinterpret_cast<const uint2*>(g_x2 + (size_t)sv * OUT_DIM + hl * 4);
                float2 f0 = __half22float2(*reinterpret_cast<__half2*>(&pk.x));
                float2 f1 = __half22float2(*reinterpret_cast<__half2*>(&pk.y));
                ax += f0.x; ay += f0.y; az += f1.x; aw += f1.y;
            }
        }
    }
    ax += __shfl_down_sync(0xffffffff, ax, 16);
    ay += __shfl_down_sync(0xffffffff, ay, 16);
    az += __shfl_down_sync(0xffffffff, az, 16);
    aw += __shfl_down_sync(0xffffffff, aw, 16);

    bool fin = (lane < OUT_DIM / 4);
    float sc = rsqrtf(fmaxf((float)(end - start), 1.0f));
    float4 x = make_float4(-FLT_MAX, -FLT_MAX, -FLT_MAX, -FLT_MAX);
    if (fin) {
        float4 bb = *reinterpret_cast<const float4*>(b2 + lane * 4);
        x.x = ax * sc + bb.x;
        x.y = ay * sc + bb.y;
        x.z = az * sc + bb.z;
        x.w = aw * sc + bb.w;
    }

    float m = fmaxf(fmaxf(x.x, x.y), fmaxf(x.z, x.w));
#pragma unroll
    for (int o = 16; o > 0; o >>= 1) m = fmaxf(m, __shfl_xor_sync(0xffffffff, m, o));

    float se = 0.f;
    if (fin) se = expf(x.x - m) + expf(x.y - m) + expf(x.z - m) + expf(x.w - m);
#pragma unroll
    for (int o = 16; o > 0; o >>= 1) se += __shfl_xor_sync(0xffffffff, se, o);

    float lse = m + logf(se);
    if (fin) {
        float4 r = make_float4(x.x - lse, x.y - lse, x.z - lse, x.w - lse);
        *reinterpret_cast<float4*>(out + (size_t)n * OUT_DIM + lane * 4) = r;
    }
}

// ---------------------------------------------------------------------------
extern "C" void kernel_launch(void* const* d_in, const int* in_sizes, int n_in,
                              void* d_out, int out_size) {
    const float* h  = (const float*)d_in[0];
    const float* W1 = (const float*)d_in[1];
    const float* b1 = (const float*)d_in[2];
    const float* W2 = (const float*)d_in[3];
    const float* b2 = (const float*)d_in[4];
    const int* src  = (const int*)d_in[5];
    const int* dst  = (const int*)d_in[6];
    float* out      = (float*)d_out;
    const int E     = in_sizes[5];
    const int E4    = E / 4;

    zero_counts_kernel<<<(N_NODES + 255) / 256, 256>>>();                                    // 1
    degree_kernel<<<(E4 + 255) / 256, 256>>>((const int4*)src, (const int4*)dst, E4);        // 2
    scan1_kernel<<<NB_SCAN, 1024>>>();                                                       // 3
    gemm1_kernel<<<(N_NODES + G1_BM - 1) / G1_BM, 128>>>(h, W1);                             // 4 (profiled)
    scan2_kernel<<<1, 128>>>();                                                              // 5
    scan3_kernel<<<(N_NODES + 255) / 256, 256>>>();                                          // 6
    scatter_kernel<<<(E4 + 255) / 256, 256>>>((const int4*)src, (const int4*)dst, E4);       // 7
    spmm1_csr_kernel<<<(N_NODES * 32 + 255) / 256, 256>>>(b1);                               // 8
    gemm2_kernel<<<(N_NODES + 127) / 128, 128>>>(W2);                                        // 9
    spmm2_csr_kernel<<<(N_NODES * 32 + 255) / 256, 256>>>(out, b2);                          // 10
}

// round 10
// speedup vs baseline: 1.4123x; 1.3207x over previous
#include <cuda_runtime.h>
#include <cuda_fp16.h>
#include <math.h>
#include <float.h>
#include <stdint.h>

#define N_NODES 100000
#define IN_DIM  256
#define HID     128
#define OUT_DIM 40
#define E_MAX   3200000
#define NB_SCAN ((N_NODES + 1023) / 1024)   // 98

typedef unsigned long long u64;

// ---------------- scratch (device globals, allocation-free) ----------------
__device__ int   g_cnt_in[N_NODES];
__device__ int   g_cnt_out[N_NODES];
__device__ int   g_incl[N_NODES];
__device__ int   g_bsum[NB_SCAN];
__device__ int   g_boff[NB_SCAN];
__device__ int   g_row_off[N_NODES + 1];
__device__ int   g_cursor[N_NODES];
__device__ int   g_csr_src[E_MAX];
__device__ __half g_w1h[(size_t)IN_DIM * HID];     // W1 fp16 [k][n]
__device__ __half g_h1[(size_t)N_NODES * HID];     // h1 fp16 (layer-1 pre-agg)
__device__ __half g_x2[(size_t)N_NODES * OUT_DIM]; // x2 fp16 (layer-2 pre-agg)
__device__ float  g_buf2[(size_t)N_NODES * HID];   // x1 fp32

// ---------------- packed fp32x2 helpers (Blackwell FFMA2) ----------------
__device__ __forceinline__ u64 ffma2(u64 a, u64 b, u64 c) {
    u64 d;
    asm("fma.rn.f32x2 %0, %1, %2, %3;" : "=l"(d) : "l"(a), "l"(b), "l"(c));
    return d;
}
__device__ __forceinline__ u64 dup2(float v) {
    unsigned int b = __float_as_uint(v);
    return ((u64)b << 32) | (u64)b;
}
__device__ __forceinline__ float lo2(u64 v) { return __uint_as_float((unsigned int)v); }
__device__ __forceinline__ float hi2(u64 v) { return __uint_as_float((unsigned int)(v >> 32)); }

__device__ __forceinline__ uint32_t h2u(__half2 h) {
    uint32_t u;
    memcpy(&u, &h, 4);
    return u;
}

__device__ __forceinline__ uint32_t smem_u32(const void* p) {
    uint32_t a;
    asm("{ .reg .u64 t; cvta.to.shared.u64 t, %1; cvt.u32.u64 %0, t; }" : "=r"(a) : "l"(p));
    return a;
}

// mma.sync m16n8k16 f16 x f16 -> f32
__device__ __forceinline__ void mma16816(float* c, uint32_t a0, uint32_t a1, uint32_t a2,
                                         uint32_t a3, uint32_t b0, uint32_t b1) {
    asm volatile("mma.sync.aligned.m16n8k16.row.col.f32.f16.f16.f32 "
                 "{%0,%1,%2,%3}, {%4,%5,%6,%7}, {%8,%9}, {%0,%1,%2,%3};"
                 : "+f"(c[0]), "+f"(c[1]), "+f"(c[2]), "+f"(c[3])
                 : "r"(a0), "r"(a1), "r"(a2), "r"(a3), "r"(b0), "r"(b1));
}

// ---------------------------------------------------------------------------
__global__ void zero_counts_kernel() {
    int i = blockIdx.x * blockDim.x + threadIdx.x;
    if (i < N_NODES) { g_cnt_in[i] = 0; g_cnt_out[i] = 0; }
}

__global__ void degree_kernel(const int4* __restrict__ src4, const int4* __restrict__ dst4, int E4) {
    int i = blockIdx.x * blockDim.x + threadIdx.x;
    if (i >= E4) return;
    int4 s = src4[i], d = dst4[i];
    atomicAdd(&g_cnt_out[s.x], 1); atomicAdd(&g_cnt_out[s.y], 1);
    atomicAdd(&g_cnt_out[s.z], 1); atomicAdd(&g_cnt_out[s.w], 1);
    atomicAdd(&g_cnt_in[d.x], 1);  atomicAdd(&g_cnt_in[d.y], 1);
    atomicAdd(&g_cnt_in[d.z], 1);  atomicAdd(&g_cnt_in[d.w], 1);
}

__global__ void prep_w1h_kernel(const float* __restrict__ W1) {
    int i = blockIdx.x * blockDim.x + threadIdx.x;
    if (i < IN_DIM * HID) g_w1h[i] = __float2half(W1[i]);
}

// ---------------- CSR build (shfl scans) ----------------
__global__ __launch_bounds__(1024) void scan1_kernel() {
    __shared__ int wsum[32];
    int tid = threadIdx.x, lane = tid & 31, wid = tid >> 5;
    int i = blockIdx.x * 1024 + tid;
    int v = (i < N_NODES) ? g_cnt_in[i] : 0;
    int x = v;
#pragma unroll
    for (int o = 1; o < 32; o <<= 1) {
        int t = __shfl_up_sync(0xffffffff, x, o);
        if (lane >= o) x += t;
    }
    if (lane == 31) wsum[wid] = x;
    __syncthreads();
    if (wid == 0) {
        int w = wsum[lane];
#pragma unroll
        for (int o = 1; o < 32; o <<= 1) {
            int t = __shfl_up_sync(0xffffffff, w, o);
            if (lane >= o) w += t;
        }
        wsum[lane] = w;
    }
    __syncthreads();
    int base = (wid > 0) ? wsum[wid - 1] : 0;
    x += base;
    if (i < N_NODES) g_incl[i] = x;
    if (tid == 1023) g_bsum[blockIdx.x] = x;
}

__global__ __launch_bounds__(128) void scan2_kernel() {
    __shared__ int wsum[4];
    int tid = threadIdx.x, lane = tid & 31, wid = tid >> 5;
    int v = (tid < NB_SCAN) ? g_bsum[tid] : 0;
    int x = v;
#pragma unroll
    for (int o = 1; o < 32; o <<= 1) {
        int t = __shfl_up_sync(0xffffffff, x, o);
        if (lane >= o) x += t;
    }
    if (lane == 31) wsum[wid] = x;
    __syncthreads();
    int base = 0;
#pragma unroll
    for (int w = 0; w < 4; w++) base += (w < wid) ? wsum[w] : 0;
    if (tid < NB_SCAN) g_boff[tid] = x + base - v;   // exclusive
}

__global__ void scan3_kernel() {
    int i = blockIdx.x * blockDim.x + threadIdx.x;
    if (i >= N_NODES) return;
    int boff = g_boff[i >> 10];
    int excl = g_incl[i] - g_cnt_in[i] + boff;
    g_row_off[i] = excl;
    g_cursor[i]  = excl;
    if (i == N_NODES - 1) g_row_off[N_NODES] = g_incl[i] + boff;
}

__global__ void scatter_kernel(const int4* __restrict__ src4, const int4* __restrict__ dst4, int E4) {
    int i = blockIdx.x * blockDim.x + threadIdx.x;
    if (i >= E4) return;
    int4 s = src4[i], d = dst4[i];
    g_csr_src[atomicAdd(&g_cursor[d.x], 1)] = s.x;
    g_csr_src[atomicAdd(&g_cursor[d.y], 1)] = s.y;
    g_csr_src[atomicAdd(&g_cursor[d.z], 1)] = s.z;
    g_csr_src[atomicAdd(&g_cursor[d.w], 1)] = s.w;
}

// ---------------------------------------------------------------------------
// GEMM1 (HMMA mma.sync m16n8k16): g_h1 = fp16((h @ W1) * deg_out^-1/2)
// 256 threads = 8 warps; CTA does 128 rows; warp does 16 rows x 128 cols.
// W1 fp16 resident in padded smem [256][136] (ldmatrix conflict-free).
// A fragments loaded straight from gmem fp32 + converted (no smem, no sync).
// ---------------------------------------------------------------------------
#define G1_SMEM (IN_DIM * 136 * 2)   // 69632 bytes
__global__ __launch_bounds__(256) void gemm1_kernel(const float* __restrict__ A) {
    extern __shared__ __half Bsh[];   // [256][136]
    const int tid = threadIdx.x;
    const int wid = tid >> 5, lane = tid & 31;
    const int m0 = blockIdx.x * 128 + wid * 16;

    // preload W1 fp16 -> padded smem (row = tid)
    {
        const uint4* srcr = reinterpret_cast<const uint4*>(g_w1h + (size_t)tid * HID);
        uint4* dstr = reinterpret_cast<uint4*>(Bsh + (size_t)tid * 136);
#pragma unroll
        for (int i = 0; i < 16; i++) dstr[i] = srcr[i];
    }
    __syncthreads();

    const int g = lane >> 2, tg = lane & 3;
    const int row0 = m0 + g, row1 = m0 + g + 8;
    const bool ok0 = row0 < N_NODES, ok1 = row1 < N_NODES;
    const float* pa0 = A + (size_t)(ok0 ? row0 : 0) * IN_DIM + tg * 2;
    const float* pa1 = A + (size_t)(ok1 ? row1 : 0) * IN_DIM + tg * 2;

    // B ldmatrix per-lane address components
    const int k_off = (lane & 7) + ((lane >> 3) & 1) * 8;
    const int n_off = (lane >> 4) * 8;

    float acc[16][4];
#pragma unroll
    for (int t = 0; t < 16; t++)
#pragma unroll
        for (int j = 0; j < 4; j++) acc[t][j] = 0.f;

    const float2 z2 = make_float2(0.f, 0.f);
    for (int kt = 0; kt < 16; kt++) {
        const int k0 = kt * 16;
        float2 f;
        f = ok0 ? *reinterpret_cast<const float2*>(pa0 + k0) : z2;
        uint32_t a0 = h2u(__floats2half2_rn(f.x, f.y));
        f = ok1 ? *reinterpret_cast<const float2*>(pa1 + k0) : z2;
        uint32_t a1 = h2u(__floats2half2_rn(f.x, f.y));
        f = ok0 ? *reinterpret_cast<const float2*>(pa0 + k0 + 8) : z2;
        uint32_t a2 = h2u(__floats2half2_rn(f.x, f.y));
        f = ok1 ? *reinterpret_cast<const float2*>(pa1 + k0 + 8) : z2;
        uint32_t a3 = h2u(__floats2half2_rn(f.x, f.y));

        uint32_t base = smem_u32(Bsh + (size_t)(k0 + k_off) * 136 + n_off);
#pragma unroll
        for (int p = 0; p < 8; p++) {
            uint32_t b0, b1, b2, b3;
            asm volatile("ldmatrix.sync.aligned.m8n8.x4.trans.shared.b16 {%0,%1,%2,%3}, [%4];"
                         : "=r"(b0), "=r"(b1), "=r"(b2), "=r"(b3)
                         : "r"(base + p * 32));
            mma16816(acc[2 * p],     a0, a1, a2, a3, b0, b1);
            mma16816(acc[2 * p + 1], a0, a1, a2, a3, b2, b3);
        }
    }

    float s0 = ok0 ? rsqrtf(fmaxf((float)g_cnt_out[row0], 1.f)) : 0.f;
    float s1 = ok1 ? rsqrtf(fmaxf((float)g_cnt_out[row1], 1.f)) : 0.f;
#pragma unroll
    for (int t = 0; t < 16; t++) {
        int col = t * 8 + tg * 2;
        if (ok0)
            *reinterpret_cast<__half2*>(g_h1 + (size_t)row0 * HID + col) =
                __floats2half2_rn(acc[t][0] * s0, acc[t][1] * s0);
        if (ok1)
            *reinterpret_cast<__half2*>(g_h1 + (size_t)row1 * HID + col) =
                __floats2half2_rn(acc[t][2] * s1, acc[t][3] * s1);
    }
}

// ---------------------------------------------------------------------------
// SpMM1 (pull, CSR, fp16 gather): warp per dst node, fused norm+bias+relu.
// ---------------------------------------------------------------------------
__global__ __launch_bounds__(256) void spmm1_csr_kernel(const float* __restrict__ b1) {
    int n = (blockIdx.x * blockDim.x + threadIdx.x) >> 5;
    if (n >= N_NODES) return;
    int lane = threadIdx.x & 31;
    int start = g_row_off[n];
    int end   = g_row_off[n + 1];

    float ax = 0.f, ay = 0.f, az = 0.f, aw = 0.f;
    for (int j = start; j < end; j += 32) {
        int s = 0;
        if (j + lane < end) s = __ldg(&g_csr_src[j + lane]);
        int cnt = min(32, end - j);
        for (int k = 0; k < cnt; k++) {
            int sv = __shfl_sync(0xffffffff, s, k);
            uint2 pk = *reinterpret_cast<const uint2*>(g_h1 + (size_t)sv * HID + lane * 4);
            float2 f0 = __half22float2(*reinterpret_cast<__half2*>(&pk.x));
            float2 f1 = __half22float2(*reinterpret_cast<__half2*>(&pk.y));
            ax += f0.x; ay += f0.y; az += f1.x; aw += f1.y;
        }
    }

    float sc = rsqrtf(fmaxf((float)(end - start), 1.0f));
    float4 bb = *reinterpret_cast<const float4*>(b1 + lane * 4);
    float4 o;
    o.x = fmaxf(ax * sc + bb.x, 0.f);
    o.y = fmaxf(ay * sc + bb.y, 0.f);
    o.z = fmaxf(az * sc + bb.z, 0.f);
    o.w = fmaxf(aw * sc + bb.w, 0.f);
    *reinterpret_cast<float4*>(g_buf2 + (size_t)n * HID + lane * 4) = o;
}

// ---------------------------------------------------------------------------
// GEMM2 (FFMA2): g_x2 = fp16((x1 @ W2) * deg_out^-1/2)
// ---------------------------------------------------------------------------
__global__ __launch_bounds__(128) void gemm2_kernel(const float* __restrict__ W2) {
    __shared__ float Ws[HID * OUT_DIM];
    const int tid = threadIdx.x;
    for (int i = tid; i < HID * OUT_DIM; i += 128) Ws[i] = W2[i];
    __syncthreads();

    int row = blockIdx.x * 128 + tid;
    if (row >= N_NODES) return;

    u64 acc[OUT_DIM / 2];
#pragma unroll
    for (int c = 0; c < OUT_DIM / 2; c++) acc[c] = 0ull;

    const float* xr = g_buf2 + (size_t)row * HID;
#pragma unroll 4
    for (int k = 0; k < HID; k += 4) {
        float4 xv = *reinterpret_cast<const float4*>(xr + k);
        u64 xs0 = dup2(xv.x), xs1 = dup2(xv.y), xs2 = dup2(xv.z), xs3 = dup2(xv.w);
        const u64* w0 = reinterpret_cast<const u64*>(&Ws[(k + 0) * OUT_DIM]);
        const u64* w1 = reinterpret_cast<const u64*>(&Ws[(k + 1) * OUT_DIM]);
        const u64* w2 = reinterpret_cast<const u64*>(&Ws[(k + 2) * OUT_DIM]);
        const u64* w3 = reinterpret_cast<const u64*>(&Ws[(k + 3) * OUT_DIM]);
#pragma unroll
        for (int c = 0; c < OUT_DIM / 2; c++) {
            acc[c] = ffma2(xs0, w0[c], acc[c]);
            acc[c] = ffma2(xs1, w1[c], acc[c]);
            acc[c] = ffma2(xs2, w2[c], acc[c]);
            acc[c] = ffma2(xs3, w3[c], acc[c]);
        }
    }

    float s = rsqrtf(fmaxf((float)g_cnt_out[row], 1.0f));
#pragma unroll
    for (int q = 0; q < 5; q++) {
        __half2 h0 = __floats2half2_rn(lo2(acc[q * 4 + 0]) * s, hi2(acc[q * 4 + 0]) * s);
        __half2 h1 = __floats2half2_rn(lo2(acc[q * 4 + 1]) * s, hi2(acc[q * 4 + 1]) * s);
        __half2 h2 = __floats2half2_rn(lo2(acc[q * 4 + 2]) * s, hi2(acc[q * 4 + 2]) * s);
        __half2 h3 = __floats2half2_rn(lo2(acc[q * 4 + 3]) * s, hi2(acc[q * 4 + 3]) * s);
        uint4 pk = make_uint4(h2u(h0), h2u(h1), h2u(h2), h2u(h3));
        *reinterpret_cast<uint4*>(g_x2 + (size_t)row * OUT_DIM + q * 8) = pk;
    }
}

// ---------------------------------------------------------------------------
// SpMM2 (pull, CSR, fp16 gather) + fused norm + bias + log_softmax.
// ---------------------------------------------------------------------------
__global__ __launch_bounds__(256) void spmm2_csr_kernel(float* __restrict__ out,
                                                        const float* __restrict__ b2) {
    int n = (blockIdx.x * blockDim.x + threadIdx.x) >> 5;
    if (n >= N_NODES) return;
    int lane = threadIdx.x & 31;
    int half = lane >> 4;
    int hl   = lane & 15;
    bool act = hl < (OUT_DIM / 4);
    int start = g_row_off[n];
    int end   = g_row_off[n + 1];

    float ax = 0.f, ay = 0.f, az = 0.f, aw = 0.f;
    for (int j = start; j < end; j += 32) {
        int s = 0;
        if (j + lane < end) s = __ldg(&g_csr_src[j + lane]);
        int cnt = min(32, end - j);
        for (int k = 0; k < cnt; k += 2) {
            int idx = k + half;
            bool ok = act && (idx < cnt);
            int sv = __shfl_sync(0xffffffff, s, idx < cnt ? idx : k);
            if (ok) {
                uint2 pk = *reinterpret_cast<const uint2*>(g_x2 + (size_t)sv * OUT_DIM + hl * 4);
                float2 f0 = __half22float2(*reinterpret_cast<__half2*>(&pk.x));
                float2 f1 = __half22float2(*reinterpret_cast<__half2*>(&pk.y));
                ax += f0.x; ay += f0.y; az += f1.x; aw += f1.y;
            }
        }
    }
    ax += __shfl_down_sync(0xffffffff, ax, 16);
    ay += __shfl_down_sync(0xffffffff, ay, 16);
    az += __shfl_down_sync(0xffffffff, az, 16);
    aw += __shfl_down_sync(0xffffffff, aw, 16);

    bool fin = (lane < OUT_DIM / 4);
    float sc = rsqrtf(fmaxf((float)(end - start), 1.0f));
    float4 x = make_float4(-FLT_MAX, -FLT_MAX, -FLT_MAX, -FLT_MAX);
    if (fin) {
        float4 bb = *reinterpret_cast<const float4*>(b2 + lane * 4);
        x.x = ax * sc + bb.x;
        x.y = ay * sc + bb.y;
        x.z = az * sc + bb.z;
        x.w = aw * sc + bb.w;
    }

    float m = fmaxf(fmaxf(x.x, x.y), fmaxf(x.z, x.w));
#pragma unroll
    for (int o = 16; o > 0; o >>= 1) m = fmaxf(m, __shfl_xor_sync(0xffffffff, m, o));

    float se = 0.f;
    if (fin) se = expf(x.x - m) + expf(x.y - m) + expf(x.z - m) + expf(x.w - m);
#pragma unroll
    for (int o = 16; o > 0; o >>= 1) se += __shfl_xor_sync(0xffffffff, se, o);

    float lse = m + logf(se);
    if (fin) {
        float4 r = make_float4(x.x - lse, x.y - lse, x.z - lse, x.w - lse);
        *reinterpret_cast<float4*>(out + (size_t)n * OUT_DIM + lane * 4) = r;
    }
}

// ---------------------------------------------------------------------------
extern "C" void kernel_launch(void* const* d_in, const int* in_sizes, int n_in,
                              void* d_out, int out_size) {
    const float* h  = (const float*)d_in[0];
    const float* W1 = (const float*)d_in[1];
    const float* b1 = (const float*)d_in[2];
    const float* W2 = (const float*)d_in[3];
    const float* b2 = (const float*)d_in[4];
    const int* src  = (const int*)d_in[5];
    const int* dst  = (const int*)d_in[6];
    float* out      = (float*)d_out;
    const int E     = in_sizes[5];
    const int E4    = E / 4;

    cudaFuncSetAttribute(gemm1_kernel, cudaFuncAttributeMaxDynamicSharedMemorySize, G1_SMEM);

    zero_counts_kernel<<<(N_NODES + 255) / 256, 256>>>();                                    // 1
    degree_kernel<<<(E4 + 255) / 256, 256>>>((const int4*)src, (const int4*)dst, E4);        // 2
    prep_w1h_kernel<<<(IN_DIM * HID + 255) / 256, 256>>>(W1);                                // 3
    gemm1_kernel<<<(N_NODES + 127) / 128, 256, G1_SMEM>>>(h);                                // 4 (profiled)
    scan1_kernel<<<NB_SCAN, 1024>>>();                                                       // 5
    scan2_kernel<<<1, 128>>>();                                                              // 6
    scan3_kernel<<<(N_NODES + 255) / 256, 256>>>();                                          // 7
    scatter_kernel<<<(E4 + 255) / 256, 256>>>((const int4*)src, (const int4*)dst, E4);       // 8
    spmm1_csr_kernel<<<(N_NODES * 32 + 255) / 256, 256>>>(b1);                               // 9
    gemm2_kernel<<<(N_NODES + 127) / 128, 128>>>(W2);                                        // 10
    spmm2_csr_kernel<<<(N_NODES * 32 + 255) / 256, 256>>>(out, b2);                          // 11
}

// round 11
// speedup vs baseline: 1.6018x; 1.1342x over previous
#include <cuda_runtime.h>
#include <cuda_fp16.h>
#include <math.h>
#include <float.h>
#include <stdint.h>

#define N_NODES 100000
#define IN_DIM  256
#define HID     128
#define OUT_DIM 40
#define E_MAX   3200000
#define NB_SCAN ((N_NODES + 1023) / 1024)   // 98

typedef unsigned long long u64;

// ---------------- scratch (device globals, allocation-free) ----------------
__device__ int   g_cnt_in[N_NODES];
__device__ int   g_cnt_out[N_NODES];
__device__ int   g_incl[N_NODES];
__device__ int   g_bsum[NB_SCAN];
__device__ int   g_boff[NB_SCAN];
__device__ int   g_row_off[N_NODES + 1];
__device__ int   g_cursor[N_NODES];
__device__ int   g_csr_src[E_MAX];
__device__ __half g_w1h[(size_t)IN_DIM * HID];     // W1 fp16 [k][n]
__device__ __half g_w2h[(size_t)HID * OUT_DIM];    // W2 fp16 [k][n]
__device__ __half g_h1[(size_t)N_NODES * HID];     // h1 fp16 (layer-1 pre-agg)
__device__ __half g_x1h[(size_t)N_NODES * HID];    // x1 fp16 (gemm2 input)
__device__ __half g_x2[(size_t)N_NODES * OUT_DIM]; // x2 fp16 (layer-2 pre-agg)

// ---------------- helpers ----------------
__device__ __forceinline__ uint32_t h2u(__half2 h) {
    uint32_t u;
    memcpy(&u, &h, 4);
    return u;
}
__device__ __forceinline__ uint32_t smem_u32(const void* p) {
    uint32_t a;
    asm("{ .reg .u64 t; cvta.to.shared.u64 t, %1; cvt.u32.u64 %0, t; }" : "=r"(a) : "l"(p));
    return a;
}
// mma.sync m16n8k16 f16 x f16 -> f32
__device__ __forceinline__ void mma16816(float* c, uint32_t a0, uint32_t a1, uint32_t a2,
                                         uint32_t a3, uint32_t b0, uint32_t b1) {
    asm volatile("mma.sync.aligned.m16n8k16.row.col.f32.f16.f16.f32 "
                 "{%0,%1,%2,%3}, {%4,%5,%6,%7}, {%8,%9}, {%0,%1,%2,%3};"
                 : "+f"(c[0]), "+f"(c[1]), "+f"(c[2]), "+f"(c[3])
                 : "r"(a0), "r"(a1), "r"(a2), "r"(a3), "r"(b0), "r"(b1));
}

// ---------------------------------------------------------------------------
__global__ void zero_counts_kernel() {
    int i = blockIdx.x * blockDim.x + threadIdx.x;
    if (i < N_NODES) { g_cnt_in[i] = 0; g_cnt_out[i] = 0; }
}

__global__ void degree_kernel(const int4* __restrict__ src4, const int4* __restrict__ dst4, int E4) {
    int i = blockIdx.x * blockDim.x + threadIdx.x;
    if (i >= E4) return;
    int4 s = src4[i], d = dst4[i];
    atomicAdd(&g_cnt_out[s.x], 1); atomicAdd(&g_cnt_out[s.y], 1);
    atomicAdd(&g_cnt_out[s.z], 1); atomicAdd(&g_cnt_out[s.w], 1);
    atomicAdd(&g_cnt_in[d.x], 1);  atomicAdd(&g_cnt_in[d.y], 1);
    atomicAdd(&g_cnt_in[d.z], 1);  atomicAdd(&g_cnt_in[d.w], 1);
}

// W1 and W2 -> fp16, one pass
__global__ void prep_weights_kernel(const float* __restrict__ W1, const float* __restrict__ W2) {
    int i = blockIdx.x * blockDim.x + threadIdx.x;
    if (i < IN_DIM * HID) g_w1h[i] = __float2half(W1[i]);
    else if (i < IN_DIM * HID + HID * OUT_DIM) g_w2h[i - IN_DIM * HID] = __float2half(W2[i - IN_DIM * HID]);
}

// ---------------- CSR build (shfl scans) ----------------
__global__ __launch_bounds__(1024) void scan1_kernel() {
    __shared__ int wsum[32];
    int tid = threadIdx.x, lane = tid & 31, wid = tid >> 5;
    int i = blockIdx.x * 1024 + tid;
    int v = (i < N_NODES) ? g_cnt_in[i] : 0;
    int x = v;
#pragma unroll
    for (int o = 1; o < 32; o <<= 1) {
        int t = __shfl_up_sync(0xffffffff, x, o);
        if (lane >= o) x += t;
    }
    if (lane == 31) wsum[wid] = x;
    __syncthreads();
    if (wid == 0) {
        int w = wsum[lane];
#pragma unroll
        for (int o = 1; o < 32; o <<= 1) {
            int t = __shfl_up_sync(0xffffffff, w, o);
            if (lane >= o) w += t;
        }
        wsum[lane] = w;
    }
    __syncthreads();
    int base = (wid > 0) ? wsum[wid - 1] : 0;
    x += base;
    if (i < N_NODES) g_incl[i] = x;
    if (tid == 1023) g_bsum[blockIdx.x] = x;
}

__global__ __launch_bounds__(128) void scan2_kernel() {
    __shared__ int wsum[4];
    int tid = threadIdx.x, lane = tid & 31, wid = tid >> 5;
    int v = (tid < NB_SCAN) ? g_bsum[tid] : 0;
    int x = v;
#pragma unroll
    for (int o = 1; o < 32; o <<= 1) {
        int t = __shfl_up_sync(0xffffffff, x, o);
        if (lane >= o) x += t;
    }
    if (lane == 31) wsum[wid] = x;
    __syncthreads();
    int base = 0;
#pragma unroll
    for (int w = 0; w < 4; w++) base += (w < wid) ? wsum[w] : 0;
    if (tid < NB_SCAN) g_boff[tid] = x + base - v;   // exclusive
}

__global__ void scan3_kernel() {
    int i = blockIdx.x * blockDim.x + threadIdx.x;
    if (i >= N_NODES) return;
    int boff = g_boff[i >> 10];
    int excl = g_incl[i] - g_cnt_in[i] + boff;
    g_row_off[i] = excl;
    g_cursor[i]  = excl;
    if (i == N_NODES - 1) g_row_off[N_NODES] = g_incl[i] + boff;
}

__global__ void scatter_kernel(const int4* __restrict__ src4, const int4* __restrict__ dst4, int E4) {
    int i = blockIdx.x * blockDim.x + threadIdx.x;
    if (i >= E4) return;
    int4 s = src4[i], d = dst4[i];
    g_csr_src[atomicAdd(&g_cursor[d.x], 1)] = s.x;
    g_csr_src[atomicAdd(&g_cursor[d.y], 1)] = s.y;
    g_csr_src[atomicAdd(&g_cursor[d.z], 1)] = s.z;
    g_csr_src[atomicAdd(&g_cursor[d.w], 1)] = s.w;
}

// ---------------------------------------------------------------------------
// GEMM1 (HMMA): g_h1 = fp16((h @ W1) * deg_out^-1/2)
// ---------------------------------------------------------------------------
#define G1_SMEM (IN_DIM * 136 * 2)   // 69632 bytes
__global__ __launch_bounds__(256) void gemm1_kernel(const float* __restrict__ A) {
    extern __shared__ __half Bsh[];   // [256][136]
    const int tid = threadIdx.x;
    const int wid = tid >> 5, lane = tid & 31;
    const int m0 = blockIdx.x * 128 + wid * 16;

    {
        const uint4* srcr = reinterpret_cast<const uint4*>(g_w1h + (size_t)tid * HID);
        uint4* dstr = reinterpret_cast<uint4*>(Bsh + (size_t)tid * 136);
#pragma unroll
        for (int i = 0; i < 16; i++) dstr[i] = srcr[i];
    }
    __syncthreads();

    const int g = lane >> 2, tg = lane & 3;
    const int row0 = m0 + g, row1 = m0 + g + 8;
    const bool ok0 = row0 < N_NODES, ok1 = row1 < N_NODES;
    const float* pa0 = A + (size_t)(ok0 ? row0 : 0) * IN_DIM + tg * 2;
    const float* pa1 = A + (size_t)(ok1 ? row1 : 0) * IN_DIM + tg * 2;

    const int k_off = (lane & 7) + ((lane >> 3) & 1) * 8;
    const int n_off = (lane >> 4) * 8;

    float acc[16][4];
#pragma unroll
    for (int t = 0; t < 16; t++)
#pragma unroll
        for (int j = 0; j < 4; j++) acc[t][j] = 0.f;

    const float2 z2 = make_float2(0.f, 0.f);
    for (int kt = 0; kt < 16; kt++) {
        const int k0 = kt * 16;
        float2 f;
        f = ok0 ? *reinterpret_cast<const float2*>(pa0 + k0) : z2;
        uint32_t a0 = h2u(__floats2half2_rn(f.x, f.y));
        f = ok1 ? *reinterpret_cast<const float2*>(pa1 + k0) : z2;
        uint32_t a1 = h2u(__floats2half2_rn(f.x, f.y));
        f = ok0 ? *reinterpret_cast<const float2*>(pa0 + k0 + 8) : z2;
        uint32_t a2 = h2u(__floats2half2_rn(f.x, f.y));
        f = ok1 ? *reinterpret_cast<const float2*>(pa1 + k0 + 8) : z2;
        uint32_t a3 = h2u(__floats2half2_rn(f.x, f.y));

        uint32_t base = smem_u32(Bsh + (size_t)(k0 + k_off) * 136 + n_off);
#pragma unroll
        for (int p = 0; p < 8; p++) {
            uint32_t b0, b1, b2, b3;
            asm volatile("ldmatrix.sync.aligned.m8n8.x4.trans.shared.b16 {%0,%1,%2,%3}, [%4];"
                         : "=r"(b0), "=r"(b1), "=r"(b2), "=r"(b3)
                         : "r"(base + p * 32));
            mma16816(acc[2 * p],     a0, a1, a2, a3, b0, b1);
            mma16816(acc[2 * p + 1], a0, a1, a2, a3, b2, b3);
        }
    }

    float s0 = ok0 ? rsqrtf(fmaxf((float)g_cnt_out[row0], 1.f)) : 0.f;
    float s1 = ok1 ? rsqrtf(fmaxf((float)g_cnt_out[row1], 1.f)) : 0.f;
#pragma unroll
    for (int t = 0; t < 16; t++) {
        int col = t * 8 + tg * 2;
        if (ok0)
            *reinterpret_cast<__half2*>(g_h1 + (size_t)row0 * HID + col) =
                __floats2half2_rn(acc[t][0] * s0, acc[t][1] * s0);
        if (ok1)
            *reinterpret_cast<__half2*>(g_h1 + (size_t)row1 * HID + col) =
                __floats2half2_rn(acc[t][2] * s1, acc[t][3] * s1);
    }
}

// ---------------------------------------------------------------------------
// SpMM1 (pull, CSR, fp16 gather): warp per dst node, fused norm+bias+relu.
// Output x1 in fp16. Fast full-block path with unroll-4 for MLP.
// ---------------------------------------------------------------------------
__global__ __launch_bounds__(256) void spmm1_csr_kernel(const float* __restrict__ b1) {
    int n = (blockIdx.x * blockDim.x + threadIdx.x) >> 5;
    if (n >= N_NODES) return;
    int lane = threadIdx.x & 31;
    int start = g_row_off[n];
    int end   = g_row_off[n + 1];

    float ax = 0.f, ay = 0.f, az = 0.f, aw = 0.f;
    for (int j = start; j < end; j += 32) {
        int s = 0;
        if (j + lane < end) s = __ldg(&g_csr_src[j + lane]);
        int cnt = min(32, end - j);
        if (cnt == 32) {
#pragma unroll 4
            for (int k = 0; k < 32; k++) {
                int sv = __shfl_sync(0xffffffff, s, k);
                uint2 pk = *reinterpret_cast<const uint2*>(g_h1 + (size_t)sv * HID + lane * 4);
                float2 f0 = __half22float2(*reinterpret_cast<__half2*>(&pk.x));
                float2 f1 = __half22float2(*reinterpret_cast<__half2*>(&pk.y));
                ax += f0.x; ay += f0.y; az += f1.x; aw += f1.y;
            }
        } else {
            for (int k = 0; k < cnt; k++) {
                int sv = __shfl_sync(0xffffffff, s, k);
                uint2 pk = *reinterpret_cast<const uint2*>(g_h1 + (size_t)sv * HID + lane * 4);
                float2 f0 = __half22float2(*reinterpret_cast<__half2*>(&pk.x));
                float2 f1 = __half22float2(*reinterpret_cast<__half2*>(&pk.y));
                ax += f0.x; ay += f0.y; az += f1.x; aw += f1.y;
            }
        }
    }

    float sc = rsqrtf(fmaxf((float)(end - start), 1.0f));
    float4 bb = *reinterpret_cast<const float4*>(b1 + lane * 4);
    float ox = fmaxf(ax * sc + bb.x, 0.f);
    float oy = fmaxf(ay * sc + bb.y, 0.f);
    float oz = fmaxf(az * sc + bb.z, 0.f);
    float ow = fmaxf(aw * sc + bb.w, 0.f);
    uint2 pk = make_uint2(h2u(__floats2half2_rn(ox, oy)), h2u(__floats2half2_rn(oz, ow)));
    *reinterpret_cast<uint2*>(g_x1h + (size_t)n * HID + lane * 4) = pk;
}

// ---------------------------------------------------------------------------
// GEMM2 (HMMA): g_x2 = fp16((x1 @ W2) * deg_out^-1/2)
// W2 fp16 in smem [128][56] (pad cols 40->48 compute, 56 stride: conflict-free).
// A (x1 fp16) loaded directly from gmem per fragment.
// ---------------------------------------------------------------------------
#define G2_NPAD 56
__global__ __launch_bounds__(256) void gemm2_kernel() {
    __shared__ __half Wsh[HID * G2_NPAD];   // 14336 B
    const int tid = threadIdx.x;
    const int wid = tid >> 5, lane = tid & 31;
    const int m0 = blockIdx.x * 128 + wid * 16;

    for (int i = tid; i < HID * G2_NPAD; i += 256) {
        int r = i / G2_NPAD, c = i % G2_NPAD;
        Wsh[i] = (c < OUT_DIM) ? g_w2h[r * OUT_DIM + c] : __float2half(0.f);
    }
    __syncthreads();

    const int g = lane >> 2, tg = lane & 3;
    const int row0 = m0 + g, row1 = m0 + g + 8;
    const bool ok0 = row0 < N_NODES, ok1 = row1 < N_NODES;
    const __half* px0 = g_x1h + (size_t)(ok0 ? row0 : 0) * HID + tg * 2;
    const __half* px1 = g_x1h + (size_t)(ok1 ? row1 : 0) * HID + tg * 2;

    const int k_off = (lane & 7) + ((lane >> 3) & 1) * 8;
    const int n_off = (lane >> 4) * 8;

    float acc[6][4];
#pragma unroll
    for (int t = 0; t < 6; t++)
#pragma unroll
        for (int j = 0; j < 4; j++) acc[t][j] = 0.f;

    for (int kt = 0; kt < 8; kt++) {
        const int k0 = kt * 16;
        uint32_t a0 = ok0 ? *reinterpret_cast<const uint32_t*>(px0 + k0) : 0u;
        uint32_t a1 = ok1 ? *reinterpret_cast<const uint32_t*>(px1 + k0) : 0u;
        uint32_t a2 = ok0 ? *reinterpret_cast<const uint32_t*>(px0 + k0 + 8) : 0u;
        uint32_t a3 = ok1 ? *reinterpret_cast<const uint32_t*>(px1 + k0 + 8) : 0u;

        uint32_t base = smem_u32(Wsh + (size_t)(k0 + k_off) * G2_NPAD + n_off);
#pragma unroll
        for (int p = 0; p < 3; p++) {
            uint32_t b0, b1, b2, b3;
            asm volatile("ldmatrix.sync.aligned.m8n8.x4.trans.shared.b16 {%0,%1,%2,%3}, [%4];"
                         : "=r"(b0), "=r"(b1), "=r"(b2), "=r"(b3)
                         : "r"(base + p * 32));
            mma16816(acc[2 * p],     a0, a1, a2, a3, b0, b1);
            mma16816(acc[2 * p + 1], a0, a1, a2, a3, b2, b3);
        }
    }

    float s0 = ok0 ? rsqrtf(fmaxf((float)g_cnt_out[row0], 1.f)) : 0.f;
    float s1 = ok1 ? rsqrtf(fmaxf((float)g_cnt_out[row1], 1.f)) : 0.f;
#pragma unroll
    for (int t = 0; t < 5; t++) {   // only first 40 cols are real
        int col = t * 8 + tg * 2;
        if (ok0)
            *reinterpret_cast<__half2*>(g_x2 + (size_t)row0 * OUT_DIM + col) =
                __floats2half2_rn(acc[t][0] * s0, acc[t][1] * s0);
        if (ok1)
            *reinterpret_cast<__half2*>(g_x2 + (size_t)row1 * OUT_DIM + col) =
                __floats2half2_rn(acc[t][2] * s1, acc[t][3] * s1);
    }
}

// ---------------------------------------------------------------------------
// SpMM2 (pull, CSR, fp16 gather) + fused norm + bias + log_softmax.
// Dual-edge per iter with unroll for MLP.
// ---------------------------------------------------------------------------
__global__ __launch_bounds__(256) void spmm2_csr_kernel(float* __restrict__ out,
                                                        const float* __restrict__ b2) {
    int n = (blockIdx.x * blockDim.x + threadIdx.x) >> 5;
    if (n >= N_NODES) return;
    int lane = threadIdx.x & 31;
    int half = lane >> 4;
    int hl   = lane & 15;
    bool act = hl < (OUT_DIM / 4);
    int start = g_row_off[n];
    int end   = g_row_off[n + 1];

    float ax = 0.f, ay = 0.f, az = 0.f, aw = 0.f;
    for (int j = start; j < end; j += 32) {
        int s = 0;
        if (j + lane < end) s = __ldg(&g_csr_src[j + lane]);
        int cnt = min(32, end - j);
        if (cnt == 32) {
#pragma unroll 4
            for (int k = 0; k < 32; k += 2) {
                int sv = __shfl_sync(0xffffffff, s, k + half);
                if (act) {
                    uint2 pk = *reinterpret_cast<const uint2*>(g_x2 + (size_t)sv * OUT_DIM + hl * 4);
                    float2 f0 = __half22float2(*reinterpret_cast<__half2*>(&pk.x));
                    float2 f1 = __half22float2(*reinterpret_cast<__half2*>(&pk.y));
                    ax += f0.x; ay += f0.y; az += f1.x; aw += f1.y;
                }
            }
        } else {
            for (int k = 0; k < cnt; k += 2) {
                int idx = k + half;
                bool ok = act && (idx < cnt);
                int sv = __shfl_sync(0xffffffff, s, idx < cnt ? idx : k);
                if (ok) {
                    uint2 pk = *reinterpret_cast<const uint2*>(g_x2 + (size_t)sv * OUT_DIM + hl * 4);
                    float2 f0 = __half22float2(*reinterpret_cast<__half2*>(&pk.x));
                    float2 f1 = __half22float2(*reinterpret_cast<__half2*>(&pk.y));
                    ax += f0.x; ay += f0.y; az += f1.x; aw += f1.y;
                }
            }
        }
    }
    ax += __shfl_down_sync(0xffffffff, ax, 16);
    ay += __shfl_down_sync(0xffffffff, ay, 16);
    az += __shfl_down_sync(0xffffffff, az, 16);
    aw += __shfl_down_sync(0xffffffff, aw, 16);

    bool fin = (lane < OUT_DIM / 4);
    float sc = rsqrtf(fmaxf((float)(end - start), 1.0f));
    float4 x = make_float4(-FLT_MAX, -FLT_MAX, -FLT_MAX, -FLT_MAX);
    if (fin) {
        float4 bb = *reinterpret_cast<const float4*>(b2 + lane * 4);
        x.x = ax * sc + bb.x;
        x.y = ay * sc + bb.y;
        x.z = az * sc + bb.z;
        x.w = aw * sc + bb.w;
    }

    float m = fmaxf(fmaxf(x.x, x.y), fmaxf(x.z, x.w));
#pragma unroll
    for (int o = 16; o > 0; o >>= 1) m = fmaxf(m, __shfl_xor_sync(0xffffffff, m, o));

    float se = 0.f;
    if (fin) se = expf(x.x - m) + expf(x.y - m) + expf(x.z - m) + expf(x.w - m);
#pragma unroll
    for (int o = 16; o > 0; o >>= 1) se += __shfl_xor_sync(0xffffffff, se, o);

    float lse = m + logf(se);
    if (fin) {
        float4 r = make_float4(x.x - lse, x.y - lse, x.z - lse, x.w - lse);
        *reinterpret_cast<float4*>(out + (size_t)n * OUT_DIM + lane * 4) = r;
    }
}

// ---------------------------------------------------------------------------
extern "C" void kernel_launch(void* const* d_in, const int* in_sizes, int n_in,
                              void* d_out, int out_size) {
    const float* h  = (const float*)d_in[0];
    const float* W1 = (const float*)d_in[1];
    const float* b1 = (const float*)d_in[2];
    const float* W2 = (const float*)d_in[3];
    const float* b2 = (const float*)d_in[4];
    const int* src  = (const int*)d_in[5];
    const int* dst  = (const int*)d_in[6];
    float* out      = (float*)d_out;
    const int E     = in_sizes[5];
    const int E4    = E / 4;

    cudaFuncSetAttribute(gemm1_kernel, cudaFuncAttributeMaxDynamicSharedMemorySize, G1_SMEM);

    const int PREP_N = IN_DIM * HID + HID * OUT_DIM;
    zero_counts_kernel<<<(N_NODES + 255) / 256, 256>>>();                                    // 1
    degree_kernel<<<(E4 + 255) / 256, 256>>>((const int4*)src, (const int4*)dst, E4);        // 2
    prep_weights_kernel<<<(PREP_N + 255) / 256, 256>>>(W1, W2);                              // 3
    gemm1_kernel<<<(N_NODES + 127) / 128, 256, G1_SMEM>>>(h);                                // 4 (profiled)
    scan1_kernel<<<NB_SCAN, 1024>>>();                                                       // 5
    scan2_kernel<<<1, 128>>>();                                                              // 6
    scan3_kernel<<<(N_NODES + 255) / 256, 256>>>();                                          // 7
    scatter_kernel<<<(E4 + 255) / 256, 256>>>((const int4*)src, (const int4*)dst, E4);       // 8
    spmm1_csr_kernel<<<(N_NODES * 32 + 255) / 256, 256>>>(b1);                               // 9
    gemm2_kernel<<<(N_NODES + 127) / 128, 256>>>();                                          // 10
    spmm2_csr_kernel<<<(N_NODES * 32 + 255) / 256, 256>>>(out, b2);                          // 11
}